// round 1
// baseline (speedup 1.0000x reference)
#include <cuda_runtime.h>

// Problem constants (fixed by the reference: B=16, T=64, C=8, dyadic order 2)
#define NB   16
#define TT   64
#define CC   8
#define NC   63    // coarse increment grid (T-1)
#define NF   252   // fine grid N = (T-1)*4
// PDE grid is (NF+1) x (NF+1); anti-diagonals d = 2 .. 2*NF (503 steps)

__device__ float g_K[NB * NB];

__global__ __launch_bounds__(256, 2)
void sig_pde_kernel(const float* __restrict__ paths) {
    __shared__ float2 coef[NC * NC];              // 31752 B: (c1,c2) per coarse cell
    __shared__ float  Xa[TT][CC], Xb[TT][CC];     // 4096 B
    __shared__ float  buf0[256], buf1[256], buf2[256]; // 3072 B rotating carries

    const int p   = blockIdx.x;
    const int a   = p >> 4;
    const int b   = p & 15;
    const int tid = threadIdx.x;

    // ---- load the two paths: X[i][c] = paths[batch][c][i] ----
    const float* pa = paths + a * (CC * TT);
    const float* pb = paths + b * (CC * TT);
    for (int e = tid; e < CC * TT; e += 256) {
        int c = e >> 6;       // channel
        int i = e & 63;       // time index
        Xa[i][c] = pa[e];
        Xb[i][c] = pb[e];
    }
    __syncthreads();

    // ---- precompute PDE coefficients per coarse cell ----
    // A = (G[u+1][v+1] + G[u][v] - G[u+1][v] - G[u][v+1]) / 16,  G = exp(-||dx||^2)
    // c1 = 1 + A/2 + A^2/12 ; c2 = 1 - A^2/12
    for (int e = tid; e < NC * NC; e += 256) {
        int u = e / NC;
        int v = e - u * NC;
        float d00 = 0.f, d01 = 0.f, d10 = 0.f, d11 = 0.f;
        #pragma unroll
        for (int c = 0; c < CC; ++c) {
            float xa0 = Xa[u][c],   xa1 = Xa[u + 1][c];
            float xb0 = Xb[v][c],   xb1 = Xb[v + 1][c];
            float t00 = xa0 - xb0;  d00 += t00 * t00;
            float t01 = xa0 - xb1;  d01 += t01 * t01;
            float t10 = xa1 - xb0;  d10 += t10 * t10;
            float t11 = xa1 - xb1;  d11 += t11 * t11;
        }
        float A = (expf(-d11) + expf(-d00) - expf(-d10) - expf(-d01)) * (1.0f / 16.0f);
        float q = A * A * (1.0f / 12.0f);
        coef[e] = make_float2(1.0f + 0.5f * A + q, 1.0f - q);
    }

    // ---- init carries (all ones, matching reference init) ----
    buf0[tid] = 1.0f;
    buf1[tid] = 1.0f;
    __syncthreads();

    float* p2 = buf0;   // diag d-2
    float* p1 = buf1;   // diag d-1
    float* cu = buf2;   // diag d

    const int  i      = tid;
    const int  im1    = (i == 0) ? 0 : i - 1;
    const float2* coefRow = &coef[(im1 >> 2) * NC];   // row (i-1)/4 (unused if i==0)
    const bool irange = (i >= 1) && (i <= NF);

    // ---- anti-diagonal wavefront ----
    for (int d = 2; d <= 2 * NF; ++d) {
        int jm = d - i - 1;                 // j - 1, where j = d - i
        float c1 = 1.0f, c2 = 1.0f;
        if (irange && (unsigned)jm < (unsigned)NF) {
            float2 cc = coefRow[jm >> 2];
            c1 = cc.x; c2 = cc.y;
        }
        float va = p1[im1];
        float vb = p1[i];
        float vc = p2[im1];
        float v  = (va + vb) * c1 - vc * c2;
        if (i == 0 || i == d) v = 1.0f;     // grid boundaries K[0,*]=K[*,0]=1
        cu[i] = v;
        __syncthreads();
        float* t = p2; p2 = p1; p1 = cu; cu = t;
    }

    if (tid == 0) g_K[p] = p1[NF];          // K[N][N] for this pair
}

__global__ void sig_reduce_kernel(float* __restrict__ out) {
    int a = threadIdx.x;
    if (a < NB) {
        float s = 0.0f;
        #pragma unroll
        for (int b = 0; b < NB; ++b) s += g_K[a * NB + b];
        out[2 * a]     = g_K[a * NB + a];        // diagonal
        out[2 * a + 1] = s * (1.0f / (float)NB); // row mean
    }
}

extern "C" void kernel_launch(void* const* d_in, const int* in_sizes, int n_in,
                              void* d_out, int out_size) {
    const float* paths = (const float*)d_in[0];
    sig_pde_kernel<<<NB * NB, 256>>>(paths);
    sig_reduce_kernel<<<1, 32>>>((float*)d_out);
}

// round 2
// speedup vs baseline: 1.6621x; 1.6621x over previous
#include <cuda_runtime.h>

// Problem constants (fixed by reference: B=16, T=64, C=8, dyadic order 2)
#define NB     16
#define TT     64
#define CC     8
#define NC     63            // coarse increment grid (T-1)
#define NF     252           // fine grid N = (T-1)*4
#define NPAIRS 136           // a <= b pairs (K is symmetric)
#define NSTEPS (NF + 31)     // 283 skewed wavefront steps

__device__ float g_K[NB * NB];
__device__ int   g_count = 0;

__global__ __launch_bounds__(128, 1)
void sig_fused_kernel(const float* __restrict__ paths, float* __restrict__ out) {
    __shared__ float2 coef[NC * NC];           // (c1,c2) per coarse cell, 31752 B
    __shared__ float  Xa[TT][CC], Xb[TT][CC];  // staged paths
    __shared__ int    s_last;

    const int tid = threadIdx.x;

    // ---- map block -> ordered pair (a <= b) ----
    int idx = blockIdx.x;
    int a = 0;
    while (idx >= NB - a) { idx -= NB - a; ++a; }
    const int b = a + idx;

    // ---- stage the two paths: X[i][c] = paths[batch][c][i] ----
    const float* pa = paths + a * (CC * TT);
    const float* pb = paths + b * (CC * TT);
    for (int e = tid; e < CC * TT; e += 128) {
        int c = e >> 6;   // channel
        int i = e & 63;   // time index
        Xa[i][c] = pa[e];
        Xb[i][c] = pb[e];
    }
    __syncthreads();

    // ---- precompute PDE coefficients per coarse cell (all 4 warps) ----
    // A = (G11 + G00 - G10 - G01)/16, G = exp(-||dx||^2)
    // c1 = 1 + A/2 + A^2/12 ; c2 = 1 - A^2/12
    for (int e = tid; e < NC * NC; e += 128) {
        int u = e / NC;
        int v = e - u * NC;
        float d00 = 0.f, d01 = 0.f, d10 = 0.f, d11 = 0.f;
        #pragma unroll
        for (int c = 0; c < CC; ++c) {
            float xa0 = Xa[u][c],   xa1 = Xa[u + 1][c];
            float xb0 = Xb[v][c],   xb1 = Xb[v + 1][c];
            float t00 = xa0 - xb0;  d00 += t00 * t00;
            float t01 = xa0 - xb1;  d01 += t01 * t01;
            float t10 = xa1 - xb0;  d10 += t10 * t10;
            float t11 = xa1 - xb1;  d11 += t11 * t11;
        }
        float A = (expf(-d11) + expf(-d00) - expf(-d10) - expf(-d01)) * (1.0f / 16.0f);
        float q = A * A * (1.0f / 12.0f);
        coef[e] = make_float2(1.0f + 0.5f * A + q, 1.0f - q);
    }
    __syncthreads();

    // ---- warp 0: barrier-free skewed wavefront, lane l owns rows 8l+1 .. 8l+8 ----
    float result = 0.0f;
    if (tid < 32) {
        const int l = tid;
        const float2* rowA = &coef[(2 * l) * NC];
        const float2* rowB = &coef[((2 * l + 1 < NC) ? (2 * l + 1) : (NC - 1)) * NC];

        float p0 = 1.f, p1 = 1.f, p2 = 1.f, p3 = 1.f;
        float p4 = 1.f, p5 = 1.f, p6 = 1.f, p7 = 1.f;   // K[row][j-1]
        float topPrev = 1.f;                            // K[8l][j-1]
        float v7last  = 1.f;                            // bottom-row value fed to lane l+1
        float2 cA = rowA[0], cB = rowB[0];

        for (int s = 0; s < NSTEPS; ++s) {
            float topCur = __shfl_up_sync(0xffffffffu, v7last, 1);  // K[8l][j]
            if (l == 0) topCur = 1.0f;                              // row-0 boundary

            int  jm1     = s - l;                                   // j - 1
            bool started = (jm1 >= 0);
            int  jm1c    = started ? jm1 : 0;
            if ((jm1c & 3) == 0) {                                  // new coarse column
                int jc = jm1c >> 2;
                if (jc > NC - 1) jc = NC - 1;                        // tail garbage, unused
                cA = rowA[jc];
                cB = rowB[jc];
            }

            // off-chain terms: h_r = K[i][j-1]*c1 - K[i-1][j-1]*c2
            float h0 = p0 * cA.x - topPrev * cA.y;
            float h1 = p1 * cA.x - p0 * cA.y;
            float h2 = p2 * cA.x - p1 * cA.y;
            float h3 = p3 * cA.x - p2 * cA.y;
            float h4 = p4 * cB.x - p3 * cB.y;
            float h5 = p5 * cB.x - p4 * cB.y;
            float h6 = p6 * cB.x - p5 * cB.y;
            float h7 = p7 * cB.x - p6 * cB.y;
            // serial chain: v_r = fma(v_{r-1}, c1, h_r)
            float v0 = fmaf(topCur, cA.x, h0);
            float v1 = fmaf(v0, cA.x, h1);
            float v2 = fmaf(v1, cA.x, h2);
            float v3 = fmaf(v2, cA.x, h3);
            float v4 = fmaf(v3, cB.x, h4);
            float v5 = fmaf(v4, cB.x, h5);
            float v6 = fmaf(v5, cB.x, h6);
            float v7 = fmaf(v6, cB.x, h7);

            if (started) {   // predicated commit; pre-start lanes keep init state
                topPrev = topCur;
                p0 = v0; p1 = v1; p2 = v2; p3 = v3;
                p4 = v4; p5 = v5; p6 = v6; p7 = v7;
                v7last = v7;
            }
        }
        result = p3;   // lane 31, row 8*31+3+1 = 252 -> K[252][252]
    }

    if (tid == 31) {
        g_K[a * NB + b] = result;
        g_K[b * NB + a] = result;   // symmetry
    }
    __syncthreads();

    // ---- last block to finish does the (16,2) reduction ----
    if (tid == 0) {
        __threadfence();
        int prev = atomicAdd(&g_count, 1);
        s_last = (prev == NPAIRS - 1) ? 1 : 0;
    }
    __syncthreads();
    if (s_last) {
        __threadfence();
        if (tid < NB) {
            float s = 0.0f;
            #pragma unroll
            for (int bb = 0; bb < NB; ++bb) s += __ldcg(&g_K[tid * NB + bb]);
            out[2 * tid]     = __ldcg(&g_K[tid * NB + tid]);
            out[2 * tid + 1] = s * (1.0f / (float)NB);
        }
        if (tid == 0) g_count = 0;   // reset for next graph replay
    }
}

extern "C" void kernel_launch(void* const* d_in, const int* in_sizes, int n_in,
                              void* d_out, int out_size) {
    const float* paths = (const float*)d_in[0];
    sig_fused_kernel<<<NPAIRS, 128>>>(paths, (float*)d_out);
}

// round 4
// speedup vs baseline: 2.3847x; 1.4348x over previous
#include <cuda_runtime.h>

// Problem constants (fixed by reference: B=16, T=64, C=8, dyadic order 2)
#define NB     16
#define TT     64
#define CC     8
#define NC     63            // coarse increment grid (T-1)
#define NF     252           // fine grid N = (T-1)*4
#define NPAIRS 136           // a <= b pairs (K is symmetric)
#define NSTEPS (NF + 31)     // 283 skewed wavefront steps

__device__ float g_K[NB * NB];
__device__ int   g_count = 0;

__global__ __launch_bounds__(128, 1)
void sig_fused_kernel(const float* __restrict__ paths, float* __restrict__ out) {
    // Packed per-lane coefficients: pack[l*65 + idx] = {c1A, c2A, c1B, c2B}
    //   idx 0      -> identity (1,1,1,1)  [pre-start steps]
    //   idx 1..63  -> coarse column idx-1
    //   idx 64     -> identity            [tail steps, values unused]
    __shared__ float4 pack[32 * 65];                  // 33280 B
    __shared__ float  Gs[33][65];                     // 8580 B Gram strip (padded)
    __shared__ __align__(16) float Xa[TT][CC];        // 2 KB
    __shared__ __align__(16) float Xb[TT][CC];        // 2 KB
    __shared__ int    s_last;

    const int tid = threadIdx.x;

    // ---- map block -> ordered pair (a <= b) ----
    int idx = blockIdx.x;
    int a = 0;
    while (idx >= NB - a) { idx -= NB - a; ++a; }
    const int b = a + idx;

    // ---- stage the two paths: X[i][c] = paths[batch][c][i] ----
    const float* pa = paths + a * (CC * TT);
    const float* pb = paths + b * (CC * TT);
    for (int e = tid; e < CC * TT; e += 128) {
        int c = e >> 6;   // channel
        int i = e & 63;   // time index
        Xa[i][c] = pa[e];
        Xb[i][c] = pb[e];
    }
    __syncthreads();

    // Gram strip filler: Gs[u - uBase][v] = exp(-||Xa_u - Xb_v||^2)
    auto fill_gram = [&](int uBase, int nRows) {
        const float4* xa4 = (const float4*)&Xa[0][0];
        const float4* xb4 = (const float4*)&Xb[0][0];
        for (int e = tid; e < nRows * 64; e += 128) {
            int ur = e >> 6, v = e & 63;
            int u  = uBase + ur;
            float4 a0 = xa4[2 * u], a1 = xa4[2 * u + 1];
            float4 b0 = xb4[2 * v], b1 = xb4[2 * v + 1];
            float d = 0.f, t;
            t = a0.x - b0.x; d = fmaf(t, t, d);
            t = a0.y - b0.y; d = fmaf(t, t, d);
            t = a0.z - b0.z; d = fmaf(t, t, d);
            t = a0.w - b0.w; d = fmaf(t, t, d);
            t = a1.x - b1.x; d = fmaf(t, t, d);
            t = a1.y - b1.y; d = fmaf(t, t, d);
            t = a1.z - b1.z; d = fmaf(t, t, d);
            t = a1.w - b1.w; d = fmaf(t, t, d);
            Gs[ur][v] = __expf(-d);
        }
    };

    // Pack builder for 16 lanes [lBase, lBase+16); Gs holds rows uBase..uBase+nRows-1.
    // A = (G[u+1][v+1] + G[u][v] - G[u+1][v] - G[u][v+1]) / 16
    // c1 = 1 + A/2 + A^2/12 ; c2 = 1 - A^2/12
    auto build_pack = [&](int lBase, int uBase) {
        for (int e = tid; e < 16 * 65; e += 128) {
            int l  = lBase + e / 65;
            int jc = e - (e / 65) * 65;
            float4 c4 = make_float4(1.f, 1.f, 1.f, 1.f);
            if (jc >= 1 && jc <= 63) {
                int v  = jc - 1;
                int u0 = 2 * l;     if (u0 > NC - 1) u0 = NC - 1;
                int u1 = 2 * l + 1; if (u1 > NC - 1) u1 = NC - 1;
                int r0 = u0 - uBase, r1 = u1 - uBase;
                float A0 = (Gs[r0 + 1][v + 1] + Gs[r0][v] - Gs[r0 + 1][v] - Gs[r0][v + 1]) * (1.0f / 16.0f);
                float A1 = (Gs[r1 + 1][v + 1] + Gs[r1][v] - Gs[r1 + 1][v] - Gs[r1][v + 1]) * (1.0f / 16.0f);
                float q0 = A0 * A0 * (1.0f / 12.0f);
                float q1 = A1 * A1 * (1.0f / 12.0f);
                c4 = make_float4(1.0f + 0.5f * A0 + q0, 1.0f - q0,
                                 1.0f + 0.5f * A1 + q1, 1.0f - q1);
            }
            pack[l * 65 + jc] = c4;
        }
    };

    // Stage A: G rows 0..32 -> lanes 0..15 (u up to 2*15+1+1 = 32)
    fill_gram(0, 33);
    __syncthreads();
    build_pack(0, 0);
    __syncthreads();
    // Stage B: G rows 32..63 -> lanes 16..31 (u from 32 up to 63 after clamp)
    fill_gram(32, 32);
    __syncthreads();
    build_pack(16, 32);
    __syncthreads();

    // ---- phase 3: warp 0 barrier-free skewed wavefront ----
    // Lane l owns fine rows 8l+1 .. 8l+8; column j = s - l + 1 at step s.
    float result = 0.0f;
    if (tid < 32) {
        const int l = tid;
        const float4* packL = &pack[l * 65];

        float p0 = 1.f, p1 = 1.f, p2 = 1.f, p3 = 1.f;
        float p4 = 1.f, p5 = 1.f, p6 = 1.f, p7 = 1.f;
        float topPrev = 1.f;     // K[8l][j-1]
        float v7last  = 1.f;     // bottom-row value fed to lane l+1

        int t = 4 - l;           // jm1 + 4, incremented per step
        int i0 = t >> 2; i0 = i0 < 0 ? 0 : (i0 > 64 ? 64 : i0);
        float4 c = packL[i0];

        #pragma unroll 4
        for (int s = 0; s < NSTEPS; ++s) {
            float topCur = __shfl_up_sync(0xffffffffu, v7last, 1);  // K[8l][j]
            if (l == 0) topCur = 1.0f;                              // row-0 boundary

            // prefetch next step's coefficients (latency hidden by this step)
            ++t;
            int in = t >> 2; in = in < 0 ? 0 : (in > 64 ? 64 : in);
            float4 cn = packL[in];

            // off-chain terms: h_r = p_r*c1 - p_{r-1}*c2
            float h0 = fmaf(p0, c.x, -(topPrev * c.y));
            float h1 = fmaf(p1, c.x, -(p0 * c.y));
            float h2 = fmaf(p2, c.x, -(p1 * c.y));
            float h3 = fmaf(p3, c.x, -(p2 * c.y));
            float h4 = fmaf(p4, c.z, -(p3 * c.w));
            float h5 = fmaf(p5, c.z, -(p4 * c.w));
            float h6 = fmaf(p6, c.z, -(p5 * c.w));
            float h7 = fmaf(p7, c.z, -(p6 * c.w));
            // serial chain: v_r = fma(v_{r-1}, c1, h_r)
            float v0 = fmaf(topCur, c.x, h0);
            float v1 = fmaf(v0, c.x, h1);
            float v2 = fmaf(v1, c.x, h2);
            float v3 = fmaf(v2, c.x, h3);
            float v4 = fmaf(v3, c.z, h4);
            float v5 = fmaf(v4, c.z, h5);
            float v6 = fmaf(v5, c.z, h6);
            float v7 = fmaf(v6, c.z, h7);

            topPrev = topCur;
            p0 = v0; p1 = v1; p2 = v2; p3 = v3;
            p4 = v4; p5 = v5; p6 = v6; p7 = v7;
            v7last = v7;
            c = cn;
        }
        result = p3;   // lane 31, fine row 252 at column 252 -> K[N][N]
    }

    if (tid == 31) {
        g_K[a * NB + b] = result;
        g_K[b * NB + a] = result;   // symmetry
    }
    __syncthreads();

    // ---- last block to finish does the (16,2) reduction ----
    if (tid == 0) {
        __threadfence();
        int prev = atomicAdd(&g_count, 1);
        s_last = (prev == NPAIRS - 1) ? 1 : 0;
    }
    __syncthreads();
    if (s_last) {
        __threadfence();
        if (tid < NB) {
            float s = 0.0f;
            #pragma unroll
            for (int bb = 0; bb < NB; ++bb) s += __ldcg(&g_K[tid * NB + bb]);
            out[2 * tid]     = __ldcg(&g_K[tid * NB + tid]);
            out[2 * tid + 1] = s * (1.0f / (float)NB);
        }
        if (tid == 0) g_count = 0;   // reset for next graph replay
    }
}

extern "C" void kernel_launch(void* const* d_in, const int* in_sizes, int n_in,
                              void* d_out, int out_size) {
    const float* paths = (const float*)d_in[0];
    sig_fused_kernel<<<NPAIRS, 128>>>(paths, (float*)d_out);
}

// round 5
// speedup vs baseline: 2.8149x; 1.1804x over previous
#include <cuda_runtime.h>

// Problem constants (fixed by reference: B=16, T=64, C=8, dyadic order 2)
#define NB     16
#define TT     64
#define CC     8
#define NC     63            // coarse increment grid (T-1)
#define NF     252           // fine grid N = (T-1)*4
#define NPAIRS 136           // a <= b pairs (K is symmetric)
#define NIT2   157           // 2-col skewed wavefront iterations

__device__ float g_K[NB * NB];
__device__ int   g_count = 0;

__global__ __launch_bounds__(128, 1)
void sig_fused_kernel(const float* __restrict__ paths, float* __restrict__ out) {
    // Packed per-lane coefficients: pack[l*65 + idx] = {c1A, c2A, c1B, c2B}
    //   idx 0      -> identity (1,1,1,1)  [pre-start]
    //   idx 1..63  -> coarse column idx-1
    //   idx 64     -> identity            [tail, values never feed live lanes]
    __shared__ float4 pack[32 * 65];                  // 33280 B
    __shared__ float  Gs[33][65];                     // 8580 B Gram strip (padded)
    __shared__ __align__(16) float Xa[TT][CC];        // 2 KB
    __shared__ __align__(16) float Xb[TT][CC];        // 2 KB
    __shared__ int    s_last;

    const int tid = threadIdx.x;

    // ---- map block -> ordered pair (a <= b) ----
    int idx = blockIdx.x;
    int a = 0;
    while (idx >= NB - a) { idx -= NB - a; ++a; }
    const int b = a + idx;

    // ---- stage the two paths: X[i][c] = paths[batch][c][i] ----
    const float* pa = paths + a * (CC * TT);
    const float* pb = paths + b * (CC * TT);
    for (int e = tid; e < CC * TT; e += 128) {
        int c = e >> 6;
        int i = e & 63;
        Xa[i][c] = pa[e];
        Xb[i][c] = pb[e];
    }
    __syncthreads();

    // Gram strip filler: Gs[u - uBase][v] = exp(-||Xa_u - Xb_v||^2)
    auto fill_gram = [&](int uBase, int nRows) {
        const float4* xa4 = (const float4*)&Xa[0][0];
        const float4* xb4 = (const float4*)&Xb[0][0];
        for (int e = tid; e < nRows * 64; e += 128) {
            int ur = e >> 6, v = e & 63;
            int u  = uBase + ur;
            float4 a0 = xa4[2 * u], a1 = xa4[2 * u + 1];
            float4 b0 = xb4[2 * v], b1 = xb4[2 * v + 1];
            float d = 0.f, t;
            t = a0.x - b0.x; d = fmaf(t, t, d);
            t = a0.y - b0.y; d = fmaf(t, t, d);
            t = a0.z - b0.z; d = fmaf(t, t, d);
            t = a0.w - b0.w; d = fmaf(t, t, d);
            t = a1.x - b1.x; d = fmaf(t, t, d);
            t = a1.y - b1.y; d = fmaf(t, t, d);
            t = a1.z - b1.z; d = fmaf(t, t, d);
            t = a1.w - b1.w; d = fmaf(t, t, d);
            Gs[ur][v] = __expf(-d);
        }
    };

    // Pack builder for 16 lanes [lBase, lBase+16)
    auto build_pack = [&](int lBase, int uBase) {
        for (int e = tid; e < 16 * 65; e += 128) {
            int l  = lBase + e / 65;
            int jc = e - (e / 65) * 65;
            float4 c4 = make_float4(1.f, 1.f, 1.f, 1.f);
            if (jc >= 1 && jc <= 63) {
                int v  = jc - 1;
                int u0 = 2 * l;     if (u0 > NC - 1) u0 = NC - 1;
                int u1 = 2 * l + 1; if (u1 > NC - 1) u1 = NC - 1;
                int r0 = u0 - uBase, r1 = u1 - uBase;
                float A0 = (Gs[r0 + 1][v + 1] + Gs[r0][v] - Gs[r0 + 1][v] - Gs[r0][v + 1]) * (1.0f / 16.0f);
                float A1 = (Gs[r1 + 1][v + 1] + Gs[r1][v] - Gs[r1 + 1][v] - Gs[r1][v + 1]) * (1.0f / 16.0f);
                float q0 = A0 * A0 * (1.0f / 12.0f);
                float q1 = A1 * A1 * (1.0f / 12.0f);
                c4 = make_float4(1.0f + 0.5f * A0 + q0, 1.0f - q0,
                                 1.0f + 0.5f * A1 + q1, 1.0f - q1);
            }
            pack[l * 65 + jc] = c4;
        }
    };

    fill_gram(0, 33);
    __syncthreads();
    build_pack(0, 0);
    __syncthreads();
    fill_gram(32, 32);
    __syncthreads();
    build_pack(16, 32);
    __syncthreads();

    // ---- warp 0: barrier-free wavefront, 2 fine columns per iteration ----
    // Lane l owns fine rows 8l+1..8l+8; at iter s it processes cols
    // j0 = 2(s-l)+1, j1 = j0+1 (both in coarse column (s-l)>>1).
    float result = 0.0f;
    if (tid < 32) {
        const int l = tid;
        const float4* packL = &pack[l * 65];

        float p0 = 1.f, p1 = 1.f, p2 = 1.f, p3 = 1.f;
        float p4 = 1.f, p5 = 1.f, p6 = 1.f, p7 = 1.f;   // K[rows][j0-1]
        float topPrev = 1.f;                            // K[8l][j0-1]
        float vlo = 1.f, vhi = 1.f;                     // bottom-row pair for lane l+1

        int i0 = ((-l) >> 1) + 1; i0 = i0 < 0 ? 0 : i0; // s=0 coef index
        float4 c = packL[i0];

        #pragma unroll 2
        for (int s = 0; s < NIT2; ++s) {
            float tc0 = __shfl_up_sync(0xffffffffu, vlo, 1);  // K[8l][j0]
            float tc1 = __shfl_up_sync(0xffffffffu, vhi, 1);  // K[8l][j1]
            if (l == 0) { tc0 = 1.0f; tc1 = 1.0f; }

            // prefetch next iteration's coefficients
            int tn = s + 1 - l;
            int in = (tn >> 1) + 1; in = in < 0 ? 0 : (in > 64 ? 64 : in);
            float4 cn = packL[in];

            // ---- column j0 ----
            float h0 = fmaf(p0, c.x, -(topPrev * c.y));
            float h1 = fmaf(p1, c.x, -(p0 * c.y));
            float h2 = fmaf(p2, c.x, -(p1 * c.y));
            float h3 = fmaf(p3, c.x, -(p2 * c.y));
            float h4 = fmaf(p4, c.z, -(p3 * c.w));
            float h5 = fmaf(p5, c.z, -(p4 * c.w));
            float h6 = fmaf(p6, c.z, -(p5 * c.w));
            float h7 = fmaf(p7, c.z, -(p6 * c.w));
            float v0 = fmaf(tc0, c.x, h0);
            float v1 = fmaf(v0, c.x, h1);
            float v2 = fmaf(v1, c.x, h2);
            float v3 = fmaf(v2, c.x, h3);
            float v4 = fmaf(v3, c.z, h4);
            float v5 = fmaf(v4, c.z, h5);
            float v6 = fmaf(v5, c.z, h6);
            float v7 = fmaf(v6, c.z, h7);

            // ---- column j1 (left neighbors are the fresh v's) ----
            float g0 = fmaf(v0, c.x, -(tc0 * c.y));
            float g1 = fmaf(v1, c.x, -(v0 * c.y));
            float g2 = fmaf(v2, c.x, -(v1 * c.y));
            float g3 = fmaf(v3, c.x, -(v2 * c.y));
            float g4 = fmaf(v4, c.z, -(v3 * c.w));
            float g5 = fmaf(v5, c.z, -(v4 * c.w));
            float g6 = fmaf(v6, c.z, -(v5 * c.w));
            float g7 = fmaf(v7, c.z, -(v6 * c.w));
            float w0 = fmaf(tc1, c.x, g0);
            float w1 = fmaf(w0, c.x, g1);
            float w2 = fmaf(w1, c.x, g2);
            float w3 = fmaf(w2, c.x, g3);
            float w4 = fmaf(w3, c.z, g4);
            float w5 = fmaf(w4, c.z, g5);
            float w6 = fmaf(w5, c.z, g6);
            float w7 = fmaf(w6, c.z, g7);

            topPrev = tc1;
            p0 = w0; p1 = w1; p2 = w2; p3 = w3;
            p4 = w4; p5 = w5; p6 = w6; p7 = w7;
            vlo = v7; vhi = w7;
            c = cn;
        }
        result = p3;   // lane 31: fine row 252 at column 252 -> K[N][N]
    }

    if (tid == 31) {
        g_K[a * NB + b] = result;
        g_K[b * NB + a] = result;   // symmetry
    }
    __syncthreads();

    // ---- last block to finish does the (16,2) reduction ----
    if (tid == 0) {
        __threadfence();
        int prev = atomicAdd(&g_count, 1);
        s_last = (prev == NPAIRS - 1) ? 1 : 0;
    }
    __syncthreads();
    if (s_last) {
        __threadfence();
        if (tid < NB) {
            float s = 0.0f;
            #pragma unroll
            for (int bb = 0; bb < NB; ++bb) s += __ldcg(&g_K[tid * NB + bb]);
            out[2 * tid]     = __ldcg(&g_K[tid * NB + tid]);
            out[2 * tid + 1] = s * (1.0f / (float)NB);
        }
        if (tid == 0) g_count = 0;   // reset for next graph replay
    }
}

extern "C" void kernel_launch(void* const* d_in, const int* in_sizes, int n_in,
                              void* d_out, int out_size) {
    const float* paths = (const float*)d_in[0];
    sig_fused_kernel<<<NPAIRS, 128>>>(paths, (float*)d_out);
}